// round 8
// baseline (speedup 1.0000x reference)
#include <cuda_runtime.h>
#include <math.h>

#define BATCH 8
#define NPTS  4096
#define KNN   16
#define CH    64
#define NTILE 16
#define SAMP  256            // NTILE * KNN samples per tile block
#define NBLK  2048           // BATCH * (NPTS / NTILE)

// ---------------- device scratch (no allocations allowed) ----------------
__device__ float  g_rel[BATCH * NPTS * KNN * 3];        // 6.3 MB relative vectors
__device__ float  g_h1[(size_t)NBLK * CH * SAMP];       // 134 MB pre-BN block-1 activations
__device__ double g_mom[9];                             // rel moments: x,y,z, xx,xy,xz,yy,yz,zz
__device__ float  g_w1f[CH * 3];                        // BN0-folded w1
__device__ float  g_b1f[CH];
__device__ double g_s1[CH];                             // sum h1 per channel
__device__ double g_ss1[CH];                            // sum h1^2 per channel
__device__ float  g_a1[CH];                             // BN1 scale
__device__ float  g_c1[CH];                             // BN1 shift

// ---------------- K0: zero the cross-launch accumulators ----------------
__global__ void k0_init() {
    int t = threadIdx.x;
    if (t < 9)  g_mom[t] = 0.0;
    if (t < CH) { g_s1[t] = 0.0; g_ss1[t] = 0.0; }
}

// ---------------- K1: KNN (ranks 2..17 by LARGEST distance) + rel + rel moments ----
__global__ __launch_bounds__(256) void k1_knn(const float* __restrict__ xyz) {
    extern __shared__ float4 pts[];      // 4096 x (x,y,z,|p|^2) = 64 KB
    __shared__ float sacc[9];
    const int t    = threadIdx.x;
    const int b    = blockIdx.x >> 4;    // 16 tiles of 256 queries per batch
    const int tile = blockIdx.x & 15;
    const float* xb = xyz + (size_t)b * 3 * NPTS;
    for (int n = t; n < NPTS; n += 256) {
        float x = xb[n], y = xb[NPTS + n], z = xb[2 * NPTS + n];
        pts[n] = make_float4(x, y, z, fmaf(x, x, fmaf(y, y, z * z)));
    }
    if (t < 9) sacc[t] = 0.0f;
    __syncthreads();

    const int i = tile * 256 + t;
    const float4 q = pts[i];

    float bd[17]; int bi[17];
    #pragma unroll
    for (int u = 0; u < 17; ++u) { bd[u] = -1e30f; bi[u] = 0; }
    float cmin = -1e30f; int cpos = 0;

    #pragma unroll 4
    for (int j = 0; j < NPTS; ++j) {
        float4 p = pts[j];
        float dt = fmaf(q.x, p.x, fmaf(q.y, p.y, q.z * p.z));
        float d  = q.w + p.w - 2.0f * dt;
        if (d > cmin) {            // strict >: ties keep earlier (lower) index, like jax top_k
            bd[cpos] = d; bi[cpos] = j;
            cmin = bd[0]; cpos = 0;
            #pragma unroll
            for (int u = 1; u < 17; ++u)
                if (bd[u] < cmin) { cmin = bd[u]; cpos = u; }
        }
    }

    // Drop the single farthest (idx[:, :, 0]); ties -> lowest original index.
    float mval = bd[0]; int mpos = 0;
    #pragma unroll
    for (int u = 1; u < 17; ++u)
        if (bd[u] > mval || (bd[u] == mval && bi[u] < bi[mpos])) { mval = bd[u]; mpos = u; }

    float sx=0,sy=0,sz=0,sxx=0,sxy=0,sxz=0,syy=0,syz=0,szz=0;
    float* outr = g_rel + (size_t)(b * NPTS + i) * (KNN * 3);
    int kk = 0;
    #pragma unroll
    for (int u = 0; u < 17; ++u) {
        if (u == mpos) continue;
        float4 p = pts[bi[u]];
        float rx = p.x - q.x, ry = p.y - q.y, rz = p.z - q.z;
        outr[kk*3+0] = rx; outr[kk*3+1] = ry; outr[kk*3+2] = rz;
        ++kk;
        sx += rx; sy += ry; sz += rz;
        sxx = fmaf(rx,rx,sxx); sxy = fmaf(rx,ry,sxy); sxz = fmaf(rx,rz,sxz);
        syy = fmaf(ry,ry,syy); syz = fmaf(ry,rz,syz); szz = fmaf(rz,rz,szz);
    }
    atomicAdd(&sacc[0],sx);  atomicAdd(&sacc[1],sy);  atomicAdd(&sacc[2],sz);
    atomicAdd(&sacc[3],sxx); atomicAdd(&sacc[4],sxy); atomicAdd(&sacc[5],sxz);
    atomicAdd(&sacc[6],syy); atomicAdd(&sacc[7],syz); atomicAdd(&sacc[8],szz);
    __syncthreads();
    if (t < 9) atomicAdd(&g_mom[t], (double)sacc[t]);
}

// ---------------- K2: fold block-0 BN into w1 (exact, from rel moments) ----------------
__global__ void k2_fold0(const float* __restrict__ w1, const float* __restrict__ b1,
                         const float* __restrict__ gamma, const float* __restrict__ beta) {
    int o = threadIdx.x;
    if (o >= CH) return;
    double inv = 1.0 / ((double)BATCH * NPTS * KNN);
    double m0=g_mom[0]*inv, m1=g_mom[1]*inv, m2=g_mom[2]*inv;
    double Mxx=g_mom[3]*inv, Mxy=g_mom[4]*inv, Mxz=g_mom[5]*inv;
    double Myy=g_mom[6]*inv, Myz=g_mom[7]*inv, Mzz=g_mom[8]*inv;
    double wx=w1[o*3+0], wy=w1[o*3+1], wz=w1[o*3+2], bb=b1[o];
    double wm = wx*m0 + wy*m1 + wz*m2;
    double mu = wm + bb;
    double e2 = wx*wx*Mxx + wy*wy*Myy + wz*wz*Mzz
              + 2.0*(wx*wy*Mxy + wx*wz*Mxz + wy*wz*Myz)
              + 2.0*bb*wm + bb*bb;
    double var = e2 - mu*mu;
    double a = (double)gamma[o] / sqrt(var + 1e-5);
    g_w1f[o*3+0]=(float)(a*wx); g_w1f[o*3+1]=(float)(a*wy); g_w1f[o*3+2]=(float)(a*wz);
    g_b1f[o]=(float)(a*(bb-mu) + (double)beta[o]);
}

// ---------------- K3: g1 = relu(BN0(w1 rel)); h1 = w2 g1 + b2 -> store + stats ----------------
__global__ __launch_bounds__(256) void k3_h1(const float* __restrict__ w2, const float* __restrict__ b2) {
    extern __shared__ float sm3[];
    float* g1s = sm3;                 // CH*SAMP
    float* w2t = sm3 + CH*SAMP;       // CH*CH, layout [c][o]
    __shared__ float w1fs[CH*3], b1fs[CH], b2s[CH], sh1[CH], sq1[CH];
    const int t  = threadIdx.x;
    const int b  = blockIdx.x >> 8;
    const int n0 = (blockIdx.x & 255) * NTILE;
    for (int idx = t; idx < CH*CH; idx += 256) {
        int o = idx >> 6, c = idx & 63;
        w2t[c*CH + o] = w2[idx];
    }
    if (t < CH*3) w1fs[t] = g_w1f[t];
    if (t < CH) { b1fs[t] = g_b1f[t]; b2s[t] = b2[t]; sh1[t]=0.f; sq1[t]=0.f; }
    __syncthreads();

    {   // stage 1: g1 for this tile (sample s = n_local*16 + k)
        const int nl = t >> 4, k = t & 15;
        const float* r = g_rel + (size_t)((b*NPTS + n0 + nl)*KNN + k)*3;
        float rx=r[0], ry=r[1], rz=r[2];
        #pragma unroll 16
        for (int o = 0; o < CH; ++o) {
            float h = fmaf(w1fs[o*3], rx, fmaf(w1fs[o*3+1], ry, fmaf(w1fs[o*3+2], rz, b1fs[o])));
            g1s[o*SAMP + t] = fmaxf(h, 0.0f);
        }
    }
    __syncthreads();

    // stage 2: h1 (8 samples x 8 channels per thread)
    const int og = t >> 5, sg = t & 31;
    const int o0 = og*8, s0 = sg*8;
    float acc[8][8];
    #pragma unroll
    for (int i=0;i<8;++i)
        #pragma unroll
        for (int j=0;j<8;++j) acc[i][j] = b2s[o0+j];
    for (int c = 0; c < CH; ++c) {
        float4 ga = *(const float4*)(g1s + c*SAMP + s0);
        float4 gb = *(const float4*)(g1s + c*SAMP + s0 + 4);
        float4 wa = *(const float4*)(w2t + c*CH + o0);
        float4 wb = *(const float4*)(w2t + c*CH + o0 + 4);
        float gs[8] = {ga.x,ga.y,ga.z,ga.w,gb.x,gb.y,gb.z,gb.w};
        float ws[8] = {wa.x,wa.y,wa.z,wa.w,wb.x,wb.y,wb.z,wb.w};
        #pragma unroll
        for (int i=0;i<8;++i)
            #pragma unroll
            for (int j=0;j<8;++j)
                acc[i][j] = fmaf(gs[i], ws[j], acc[i][j]);
    }
    float* hb = g_h1 + (size_t)blockIdx.x * (CH*SAMP);
    #pragma unroll
    for (int j=0;j<8;++j) {
        float s=0.f, qq=0.f;
        #pragma unroll
        for (int i=0;i<8;++i) { float h = acc[i][j]; s += h; qq = fmaf(h,h,qq); }
        atomicAdd(&sh1[o0+j], s);
        atomicAdd(&sq1[o0+j], qq);
        float4 v0 = make_float4(acc[0][j],acc[1][j],acc[2][j],acc[3][j]);
        float4 v1 = make_float4(acc[4][j],acc[5][j],acc[6][j],acc[7][j]);
        *(float4*)(hb + (o0+j)*SAMP + s0)     = v0;
        *(float4*)(hb + (o0+j)*SAMP + s0 + 4) = v1;
    }
    __syncthreads();
    if (t < CH) { atomicAdd(&g_s1[t], (double)sh1[t]); atomicAdd(&g_ss1[t], (double)sq1[t]); }
}

// ---------------- K3b: finalize block-1 BN affine ----------------
__global__ void k3b_fold1(const float* __restrict__ gamma, const float* __restrict__ beta) {
    int o = threadIdx.x;
    if (o >= CH) return;
    double inv = 1.0 / ((double)BATCH * NPTS * KNN);
    double mu  = g_s1[o] * inv;
    double var = g_ss1[o] * inv - mu*mu;
    double a = (double)gamma[o] / sqrt(var + 1e-5);
    g_a1[o] = (float)a;
    g_c1[o] = (float)((double)beta[o] - a*mu);
}

// ---------------- K4: g2 = relu(BN1(h1)); h2 = w2 g2 + b2; max over k -> out ----------------
__global__ __launch_bounds__(256) void k4_out(const float* __restrict__ w2, const float* __restrict__ b2,
                                              float* __restrict__ out) {
    extern __shared__ float sm4[];
    float* g2s = sm4;                 // CH*SAMP
    float* w2t = sm4 + CH*SAMP;       // CH*CH, [c][o]
    __shared__ float a1s[CH], c1s[CH], b2s[CH];
    __shared__ float mbuf[CH*32];
    const int t  = threadIdx.x;
    const int b  = blockIdx.x >> 8;
    const int n0 = (blockIdx.x & 255) * NTILE;
    for (int idx = t; idx < CH*CH; idx += 256) {
        int o = idx >> 6, c = idx & 63;
        w2t[c*CH + o] = w2[idx];
    }
    if (t < CH) { a1s[t]=g_a1[t]; c1s[t]=g_c1[t]; b2s[t]=b2[t]; }
    __syncthreads();

    const float* hb = g_h1 + (size_t)blockIdx.x * (CH*SAMP);
    for (int idx = t*4; idx < CH*SAMP; idx += 256*4) {
        float4 v = *(const float4*)(hb + idx);
        int o = idx >> 8;                       // 4 elems stay inside one 256-wide row
        float a = a1s[o], c = c1s[o];
        v.x = fmaxf(fmaf(a,v.x,c),0.f);
        v.y = fmaxf(fmaf(a,v.y,c),0.f);
        v.z = fmaxf(fmaf(a,v.z,c),0.f);
        v.w = fmaxf(fmaf(a,v.w,c),0.f);
        *(float4*)(g2s + idx) = v;
    }
    __syncthreads();

    const int og = t >> 5, sg = t & 31;
    const int o0 = og*8, s0 = sg*8;             // thread's 8 samples: fixed n_local, half of k
    float acc[8][8];
    #pragma unroll
    for (int i=0;i<8;++i)
        #pragma unroll
        for (int j=0;j<8;++j) acc[i][j] = b2s[o0+j];
    for (int c = 0; c < CH; ++c) {
        float4 ga = *(const float4*)(g2s + c*SAMP + s0);
        float4 gb = *(const float4*)(g2s + c*SAMP + s0 + 4);
        float4 wa = *(const float4*)(w2t + c*CH + o0);
        float4 wb = *(const float4*)(w2t + c*CH + o0 + 4);
        float gs[8] = {ga.x,ga.y,ga.z,ga.w,gb.x,gb.y,gb.z,gb.w};
        float ws[8] = {wa.x,wa.y,wa.z,wa.w,wb.x,wb.y,wb.z,wb.w};
        #pragma unroll
        for (int i=0;i<8;++i)
            #pragma unroll
            for (int j=0;j<8;++j)
                acc[i][j] = fmaf(gs[i], ws[j], acc[i][j]);
    }
    // partial max over this thread's 8 k values
    #pragma unroll
    for (int j=0;j<8;++j) {
        float m = acc[0][j];
        #pragma unroll
        for (int i=1;i<8;++i) m = fmaxf(m, acc[i][j]);
        mbuf[(o0+j)*32 + sg] = m;
    }
    __syncthreads();
    // combine the two k-halves (sg and sg^1 share the same n_local)
    if ((sg & 1) == 0) {
        const int n = n0 + (sg >> 1);
        #pragma unroll
        for (int j=0;j<8;++j) {
            int o = o0+j;
            float m = fmaxf(mbuf[o*32 + sg], mbuf[o*32 + sg + 1]);
            out[((size_t)(b*CH + o))*NPTS + n] = m;
        }
    }
}

// ---------------- launch ----------------
extern "C" void kernel_launch(void* const* d_in, const int* in_sizes, int n_in,
                              void* d_out, int out_size) {
    const float* xyz   = (const float*)d_in[0];
    const float* w1    = (const float*)d_in[1];
    const float* b1    = (const float*)d_in[2];
    const float* w2    = (const float*)d_in[3];
    const float* b2    = (const float*)d_in[4];
    const float* gamma = (const float*)d_in[5];
    const float* beta  = (const float*)d_in[6];
    float* out = (float*)d_out;
    (void)in_sizes; (void)n_in; (void)out_size;

    cudaFuncSetAttribute(k1_knn, cudaFuncAttributeMaxDynamicSharedMemorySize, 65536);
    cudaFuncSetAttribute(k3_h1,  cudaFuncAttributeMaxDynamicSharedMemorySize, 81920);
    cudaFuncSetAttribute(k4_out, cudaFuncAttributeMaxDynamicSharedMemorySize, 81920);

    k0_init<<<1, 256>>>();
    k1_knn<<<128, 256, 65536>>>(xyz);
    k2_fold0<<<1, 64>>>(w1, b1, gamma, beta);
    k3_h1<<<NBLK, 256, 81920>>>(w2, b2);
    k3b_fold1<<<1, 64>>>(gamma, beta);
    k4_out<<<NBLK, 256, 81920>>>(w2, b2, out);
}